// round 6
// baseline (speedup 1.0000x reference)
#include <cuda_runtime.h>
#include <math.h>

#define BB 16
#define SS 1024
#define DD 1024
#define CH 32
#define RR 512            // CH*BB rows per chunk
#define NC 32             // SS/CH chunks
#define SB (SS*BB)        // 16384 rows total
#define CSTEPS (RR/16)
#define ETA_F (0.01f*2.0f/(16.0f*1024.0f))

// ---------------- device scratch ----------------
__device__ float g_HT[SB*DD];
__device__ float g_STATE[SB*DD];
__device__ float g_TV[SB*DD];
__device__ float g_PROBE[SB*DD];
__device__ float g_OT[SB*DD];
__device__ float g_X1[SB*DD];
__device__ float g_H2[SB*DD];
__device__ float g_U[SB*DD];
__device__ float g_W[DD*DD];
__device__ float g_AP[2*RR*DD];
__device__ float g_E[RR*DD];
__device__ float g_Gb[NC*RR*RR];
__device__ float g_Hb[NC*RR*RR];

// ---------------- f32x2 helpers ----------------
__device__ __forceinline__ unsigned long long packf2(float x, float y) {
    unsigned long long d;
    asm("mov.b64 %0, {%1, %2};"
        : "=l"(d) : "r"(__float_as_uint(x)), "r"(__float_as_uint(y)));
    return d;
}
__device__ __forceinline__ void fma2(unsigned long long& c, unsigned long long a,
                                     unsigned long long b) {
    asm("fma.rn.f32x2 %0, %1, %2, %0;" : "+l"(c) : "l"(a), "l"(b));
}
__device__ __forceinline__ float2 unpackf2(unsigned long long d) {
    unsigned lo, hi;
    asm("mov.b64 {%0, %1}, %2;" : "=r"(lo), "=r"(hi) : "l"(d));
    return make_float2(__uint_as_float(lo), __uint_as_float(hi));
}

// ---------------- elementwise kernels ----------------
__global__ void k_prep(const float* __restrict__ x, const float* __restrict__ a1,
                       float* __restrict__ HT) {
    long i4 = (long)blockIdx.x * blockDim.x + threadIdx.x;
    long flat = i4 * 4;
    int b = (int)(flat / ((long)SS*DD));
    int t = (int)((flat / DD) % SS);
    int d = (int)(flat % DD);
    float4 xv = *(const float4*)(x + flat);
    float4 av = *(const float4*)(a1 + d);
    float4 o;
    o.x = tanhf(av.x * xv.x); o.y = tanhf(av.y * xv.y);
    o.z = tanhf(av.z * xv.z); o.w = tanhf(av.w * xv.w);
    *(float4*)(HT + ((long)(t*BB + b) * DD + d)) = o;
}

__global__ void k_tv(const float* __restrict__ ST, const float* __restrict__ noise,
                     float* __restrict__ TV) {
    long i4 = (long)blockIdx.x * blockDim.x + threadIdx.x;
    long flat = i4 * 4;
    int t = (int)(flat / ((long)BB*DD));
    int b = (int)((flat / DD) % BB);
    int d = (int)(flat % DD);
    float4 s = *(const float4*)(ST + flat);
    float4 n = *(const float4*)(noise + ((long)b*SS + t) * DD + d);
    float4 o; o.x = s.x+n.x; o.y = s.y+n.y; o.z = s.z+n.z; o.w = s.w+n.w;
    *(float4*)(TV + flat) = o;
}

__global__ void k_copyW(const float* __restrict__ src, float* __restrict__ dst) {
    long i4 = (long)blockIdx.x * blockDim.x + threadIdx.x;
    *(float4*)(dst + i4*4) = *(const float4*)(src + i4*4);
}

__global__ void k_x1h2(const float* __restrict__ OT, const float* __restrict__ x,
                       const float* __restrict__ a2,
                       float* __restrict__ X1, float* __restrict__ H2) {
    long i4 = (long)blockIdx.x * blockDim.x + threadIdx.x;
    long flat = i4 * 4;
    int b = (int)(flat / ((long)SS*DD));
    int t = (int)((flat / DD) % SS);
    int d = (int)(flat % DD);
    float4 ro = *(const float4*)(OT + ((long)(t*BB + b) * DD + d));
    float4 xv = *(const float4*)(x + flat);
    float4 av = *(const float4*)(a2 + d);
    float4 x1; x1.x = ro.x+xv.x; x1.y = ro.y+xv.y; x1.z = ro.z+xv.z; x1.w = ro.w+xv.w;
    *(float4*)(X1 + flat) = x1;
    float4 h; h.x = tanhf(av.x*x1.x); h.y = tanhf(av.y*x1.y);
    h.z = tanhf(av.z*x1.z); h.w = tanhf(av.w*x1.w);
    *(float4*)(H2 + flat) = h;
}

// ---------------- forward substitution (RR=512, 32 steps) ----------------
__global__ void __launch_bounds__(256) solve_k(const float* __restrict__ A,
                                               const float* __restrict__ G,
                                               float* __restrict__ E) {
    __shared__ __align__(16) float Es[16][RR + 4];
    const int j0 = blockIdx.x * 16;
    const int tid = threadIdx.x;
    const int r = tid >> 4, j = tid & 15;
    #pragma unroll
    for (int i = 0; i < CSTEPS; ++i) {
        int row = i*16 + r;
        Es[j][row] = A[(long)row * DD + j0 + j];
    }
    __syncthreads();
    for (int t = 1; t < CSTEPS; ++t) {
        const int row = t*16 + r;
        const float* Gr = G + (long)row * RR;
        const int kmax = t * 16;
        float sx=0.f, sy=0.f, sz=0.f, sw=0.f;
        for (int k = 0; k < kmax; k += 4) {
            float4 g = *(const float4*)(Gr + k);
            float4 e = *(const float4*)&Es[j][k];
            sx = fmaf(g.x, e.x, sx); sy = fmaf(g.y, e.y, sy);
            sz = fmaf(g.z, e.z, sz); sw = fmaf(g.w, e.w, sw);
        }
        float v = Es[j][row] - ETA_F * ((sx+sy)+(sz+sw));
        Es[j][row] = v;
        __syncthreads();
    }
    #pragma unroll
    for (int i = 0; i < CSTEPS; ++i) {
        int row = i*16 + r;
        E[(long)row * DD + j0 + j] = Es[j][row];
    }
}

// ---------------- FFMA2 (f32x2) SIMT GEMM, full fp32 ----------------
// BM=128, BN=64, 128 threads, thread tile 8x8 (4 f32x2 column pairs)
// OPA: 0 = A[M,K] row-major; 1 = A stored [K,M]; 2 = dual-source rows
// OPB: 0 = C = A*B^T, B[N,K]; 1 = C = A*B, B[K,N]
// MODE: 0 plain  1 sub P1 on rows<RR  2 block-tril mask (+skip upper tiles)
//       3 C=P1-ETA*acc (tril-K)  4 C-=ETA*acc  5 gelu  6 C=P1*acc+P2
template<int OPA,int OPB,int MODE>
__global__ void __launch_bounds__(128, 3)
gemm_f2(const float* __restrict__ A, const float* __restrict__ A2, int lda,
        const float* __restrict__ B, int ldb,
        float* __restrict__ C, int ldc,
        int M, int N, int K,
        const float* __restrict__ P1, const float* __restrict__ P2,
        long saz, long sbz, long scz)
{
    constexpr int BM = 128, BN = 64, BK = 16, T = 128;
    constexpr int LPA = BM*BK/(4*T);   // 4 float4 per thread
    constexpr int LPB = BN*BK/(4*T);   // 2

    const int m0 = blockIdx.y * BM, n0 = blockIdx.x * BN;
    if (MODE == 2 && n0 >= m0 + BM) return;     // strictly-upper tile: never read

    const int bz = blockIdx.z;
    A += (long)bz * saz;
    B += (long)bz * sbz;
    C += (long)bz * scz;

    __shared__ __align__(16) float As[2][BK][BM+4];
    __shared__ __align__(16) float Bs[2][BK][BN+4];

    const int tid = threadIdx.x;
    const int tx = tid & 7;          // 8 col-groups of 8
    const int ty = tid >> 3;         // 16 row-groups of 8

    unsigned long long acc2[8][4];
    #pragma unroll
    for (int i = 0; i < 8; ++i)
        #pragma unroll
        for (int jp = 0; jp < 4; ++jp) acc2[i][jp] = 0ull;

    int Kl = K;
    if (MODE == 3) { int kl = m0 + BM; Kl = kl < K ? kl : K; }
    const int ktiles = Kl / BK;

    float4 pa[LPA], pb[LPB];

    auto gload = [&](int k0) {
        #pragma unroll
        for (int p = 0; p < LPA; ++p) {
            const int idx = tid + p*T;
            if (OPA == 1) {
                const int ak = idx / (BM/4), amq = idx % (BM/4);
                pa[p] = *(const float4*)(A + (long)(k0 + ak) * lda + m0 + 4*amq);
            } else {
                const int am = idx / (BK/4), akq = idx % (BK/4);
                const int mg = m0 + am;
                const float* Ar;
                if (OPA == 2) Ar = (mg < RR) ? (A + (long)mg * lda)
                                             : (A2 + (long)(mg - RR) * lda);
                else          Ar = A + (long)mg * lda;
                pa[p] = *(const float4*)(Ar + k0 + 4*akq);
            }
        }
        #pragma unroll
        for (int p = 0; p < LPB; ++p) {
            const int idx = tid + p*T;
            if (OPB == 1) {
                const int bk = idx / (BN/4), bnq = idx % (BN/4);
                pb[p] = *(const float4*)(B + (long)(k0 + bk) * ldb + n0 + 4*bnq);
            } else {
                const int bn = idx / (BK/4), bkq = idx % (BK/4);
                pb[p] = *(const float4*)(B + (long)(n0 + bn) * ldb + k0 + 4*bkq);
            }
        }
    };
    auto sstore = [&](int s) {
        #pragma unroll
        for (int p = 0; p < LPA; ++p) {
            const int idx = tid + p*T;
            if (OPA == 1) {
                const int ak = idx / (BM/4), amq = idx % (BM/4);
                *(float4*)&As[s][ak][4*amq] = pa[p];
            } else {
                const int am = idx / (BK/4), akq = idx % (BK/4);
                As[s][4*akq+0][am] = pa[p].x;
                As[s][4*akq+1][am] = pa[p].y;
                As[s][4*akq+2][am] = pa[p].z;
                As[s][4*akq+3][am] = pa[p].w;
            }
        }
        #pragma unroll
        for (int p = 0; p < LPB; ++p) {
            const int idx = tid + p*T;
            if (OPB == 1) {
                const int bk = idx / (BN/4), bnq = idx % (BN/4);
                *(float4*)&Bs[s][bk][4*bnq] = pb[p];
            } else {
                const int bn = idx / (BK/4), bkq = idx % (BK/4);
                Bs[s][4*bkq+0][bn] = pb[p].x;
                Bs[s][4*bkq+1][bn] = pb[p].y;
                Bs[s][4*bkq+2][bn] = pb[p].z;
                Bs[s][4*bkq+3][bn] = pb[p].w;
            }
        }
    };
    auto compute = [&](int s) {
        #pragma unroll
        for (int kk = 0; kk < BK; ++kk) {
            float4 a0 = *(const float4*)&As[s][kk][ty*8];
            float4 a1 = *(const float4*)&As[s][kk][ty*8 + 4];
            ulonglong2 b0 = *(const ulonglong2*)&Bs[s][kk][tx*8];
            ulonglong2 b1 = *(const ulonglong2*)&Bs[s][kk][tx*8 + 4];
            unsigned long long bv[4] = {b0.x, b0.y, b1.x, b1.y};
            float af[8] = {a0.x, a0.y, a0.z, a0.w, a1.x, a1.y, a1.z, a1.w};
            #pragma unroll
            for (int i = 0; i < 8; ++i) {
                unsigned long long ad = packf2(af[i], af[i]);
                #pragma unroll
                for (int jp = 0; jp < 4; ++jp) fma2(acc2[i][jp], ad, bv[jp]);
            }
        }
    };

    gload(0);
    sstore(0);
    __syncthreads();

    for (int kt = 0; kt < ktiles; ++kt) {
        const bool more = (kt + 1 < ktiles);
        if (more) gload((kt+1)*BK);
        compute(kt & 1);
        if (more) sstore((kt+1) & 1);
        __syncthreads();
    }

    // epilogue: thread rows m0+ty*8..+8, cols n0+tx*8..+8
    #pragma unroll
    for (int i = 0; i < 8; ++i) {
        const int m = m0 + ty*8 + i;
        const int n = n0 + tx*8;
        const long ci = (long)m * ldc + n;
        float v[8];
        #pragma unroll
        for (int jp = 0; jp < 4; ++jp) {
            float2 u = unpackf2(acc2[i][jp]);
            v[2*jp] = u.x; v[2*jp+1] = u.y;
        }
        if (MODE == 1) {
            if (m < RR) {
                float4 q0 = *(const float4*)(P1 + (long)m * ldc + n);
                float4 q1 = *(const float4*)(P1 + (long)m * ldc + n + 4);
                v[0]-=q0.x; v[1]-=q0.y; v[2]-=q0.z; v[3]-=q0.w;
                v[4]-=q1.x; v[5]-=q1.y; v[6]-=q1.z; v[7]-=q1.w;
            }
        } else if (MODE == 2) {
            #pragma unroll
            for (int j = 0; j < 8; ++j)
                if (((n + j) >> 4) > (m >> 4)) v[j] = 0.f;
        } else if (MODE == 3) {
            float4 q0 = *(const float4*)(P1 + (long)m * DD + n);
            float4 q1 = *(const float4*)(P1 + (long)m * DD + n + 4);
            v[0] = q0.x - ETA_F*v[0]; v[1] = q0.y - ETA_F*v[1];
            v[2] = q0.z - ETA_F*v[2]; v[3] = q0.w - ETA_F*v[3];
            v[4] = q1.x - ETA_F*v[4]; v[5] = q1.y - ETA_F*v[5];
            v[6] = q1.z - ETA_F*v[6]; v[7] = q1.w - ETA_F*v[7];
        } else if (MODE == 4) {
            float4 c0 = *(const float4*)(C + ci);
            float4 c1 = *(const float4*)(C + ci + 4);
            v[0] = c0.x - ETA_F*v[0]; v[1] = c0.y - ETA_F*v[1];
            v[2] = c0.z - ETA_F*v[2]; v[3] = c0.w - ETA_F*v[3];
            v[4] = c1.x - ETA_F*v[4]; v[5] = c1.y - ETA_F*v[5];
            v[6] = c1.z - ETA_F*v[6]; v[7] = c1.w - ETA_F*v[7];
        } else if (MODE == 5) {
            #pragma unroll
            for (int j = 0; j < 8; ++j)
                v[j] = 0.5f*v[j]*(1.f + erff(v[j]*0.70710678118654752f));
        } else if (MODE == 6) {
            float4 p0 = *(const float4*)(P1 + ci);
            float4 p1 = *(const float4*)(P1 + ci + 4);
            float4 q0 = *(const float4*)(P2 + ci);
            float4 q1 = *(const float4*)(P2 + ci + 4);
            v[0] = p0.x*v[0] + q0.x; v[1] = p0.y*v[1] + q0.y;
            v[2] = p0.z*v[2] + q0.z; v[3] = p0.w*v[3] + q0.w;
            v[4] = p1.x*v[4] + q1.x; v[5] = p1.y*v[5] + q1.y;
            v[6] = p1.z*v[6] + q1.z; v[7] = p1.w*v[7] + q1.w;
        }
        float4 o0; o0.x = v[0]; o0.y = v[1]; o0.z = v[2]; o0.w = v[3];
        float4 o1; o1.x = v[4]; o1.y = v[5]; o1.z = v[6]; o1.w = v[7];
        *(float4*)(C + ci)     = o0;
        *(float4*)(C + ci + 4) = o1;
    }
}

// ---------------- host side ----------------
extern "C" void kernel_launch(void* const* d_in, const int* in_sizes, int n_in,
                              void* d_out, int out_size) {
    const float* x      = (const float*)d_in[0];
    const float* noise  = (const float*)d_in[1];
    const float* alpha1 = (const float*)d_in[2];
    const float* alpha2 = (const float*)d_in[3];
    const float* W_map  = (const float*)d_in[4];
    const float* W_st   = (const float*)d_in[5];
    const float* W_pr   = (const float*)d_in[6];
    const float* W_p1   = (const float*)d_in[7];
    const float* W_p2   = (const float*)d_in[8];
    float* out = (float*)d_out;

    float *HT, *ST, *TV, *PR, *OT, *X1, *H2, *U, *W, *AP, *E, *Gb, *Hb;
    cudaGetSymbolAddress((void**)&HT, g_HT);
    cudaGetSymbolAddress((void**)&ST, g_STATE);
    cudaGetSymbolAddress((void**)&TV, g_TV);
    cudaGetSymbolAddress((void**)&PR, g_PROBE);
    cudaGetSymbolAddress((void**)&OT, g_OT);
    cudaGetSymbolAddress((void**)&X1, g_X1);
    cudaGetSymbolAddress((void**)&H2, g_H2);
    cudaGetSymbolAddress((void**)&U,  g_U);
    cudaGetSymbolAddress((void**)&W,  g_W);
    cudaGetSymbolAddress((void**)&AP, g_AP);
    cudaGetSymbolAddress((void**)&E,  g_E);
    cudaGetSymbolAddress((void**)&Gb, g_Gb);
    cudaGetSymbolAddress((void**)&Hb, g_Hb);

    const int EW_BLKS = (SB*DD/4) / 256;

    // 1. h = tanh(alpha1*x), time-major
    k_prep<<<EW_BLKS, 256>>>(x, alpha1, HT);
    // 2. STATE / PROBE big GEMMs (FFMA2)
    gemm_f2<0,0,0><<<dim3(DD/64, SB/128, 1), 128>>>(
        HT, nullptr, DD, W_st, DD, ST, DD, SB, DD, DD, nullptr, nullptr, 0,0,0);
    gemm_f2<0,0,0><<<dim3(DD/64, SB/128, 1), 128>>>(
        HT, nullptr, DD, W_pr, DD, PR, DD, SB, DD, DD, nullptr, nullptr, 0,0,0);
    // 3. TV = STATE + noise
    k_tv<<<EW_BLKS, 256>>>(ST, noise, TV);
    // 4. W = W_map
    k_copyW<<<(DD*DD/4)/256, 256>>>(W_map, W);
    // 5. batched block-tril Gram + cross-Gram (upper tiles skipped)
    gemm_f2<0,0,2><<<dim3(RR/64, RR/128, NC), 128>>>(
        TV, nullptr, DD, TV, DD, Gb, RR, RR, RR, DD, nullptr, nullptr,
        (long)RR*DD, (long)RR*DD, (long)RR*RR);
    gemm_f2<0,0,2><<<dim3(RR/64, RR/128, NC), 128>>>(
        PR, nullptr, DD, TV, DD, Hb, RR, RR, RR, DD, nullptr, nullptr,
        (long)RR*DD, (long)RR*DD, (long)RR*RR);

    // 6. sequential chunk loop (32 chunks)
    for (int c = 0; c < NC; ++c) {
        const float* TVc = TV + (long)c*RR*DD;
        const float* PRc = PR + (long)c*RR*DD;
        const float* STc = ST + (long)c*RR*DD;
        // A = TVc@W^T - STATEc (rows<RR) ; P0 = PRc@W^T (rows>=RR)
        gemm_f2<2,0,1><<<dim3(DD/64, (2*RR)/128, 1), 128>>>(
            TVc, PRc, DD, W, DD, AP, DD, 2*RR, DD, DD, STc, nullptr, 0,0,0);
        // forward substitution -> E
        solve_k<<<DD/16, 256>>>(AP, Gb + (long)c*RR*RR, E);
        // readout = P0 - ETA * trilHb @ E
        gemm_f2<0,1,3><<<dim3(DD/64, RR/128, 1), 128>>>(
            Hb + (long)c*RR*RR, nullptr, RR, E, DD,
            OT + (long)c*RR*DD, DD, RR, DD, RR,
            AP + (long)RR*DD, nullptr, 0,0,0);
        // W -= ETA * E^T @ TVc
        gemm_f2<1,1,4><<<dim3(DD/64, DD/128, 1), 128>>>(
            E, nullptr, DD, TVc, DD, W, DD, DD, DD, RR, nullptr, nullptr, 0,0,0);
    }

    // 7. x1 / h2
    k_x1h2<<<EW_BLKS, 256>>>(OT, x, alpha2, X1, H2);
    // 8. U = gelu(h2 @ Wp1^T)
    gemm_f2<0,0,5><<<dim3(DD/64, SB/128, 1), 128>>>(
        H2, nullptr, DD, W_p1, DD, U, DD, SB, DD, DD, nullptr, nullptr, 0,0,0);
    // 9. out = U * (h2 @ Wp2^T) + X1
    gemm_f2<0,0,6><<<dim3(DD/64, SB/128, 1), 128>>>(
        H2, nullptr, DD, W_p2, DD, out, DD, SB, DD, DD, U, X1, 0,0,0);
}

// round 7
// speedup vs baseline: 1.5728x; 1.5728x over previous
#include <cuda_runtime.h>
#include <cuda_bf16.h>
#include <math.h>
#include <stdint.h>

#define BB 16
#define SS 1024
#define DD 1024
#define CH 32
#define RR 512            // CH*BB rows per chunk
#define NC 32             // SS/CH chunks
#define SB (SS*BB)        // 16384 rows total
#define CSTEPS (RR/16)
#define ETA_F (0.01f*2.0f/(16.0f*1024.0f))

// ---------------- device scratch ----------------
__device__ float g_HT[SB*DD];
__device__ float g_STATE[SB*DD];
__device__ float g_TV[SB*DD];
__device__ float g_PROBE[SB*DD];
__device__ float g_OT[SB*DD];
__device__ float g_X1[SB*DD];
__device__ float g_H2[SB*DD];
__device__ float g_U[SB*DD];
__device__ float g_W[DD*DD];
__device__ float g_AP[2*RR*DD];
__device__ float g_Gb[NC*RR*RR];
__device__ __nv_bfloat16 g_TVh[SB*DD];
__device__ __nv_bfloat16 g_PRh[SB*DD];
__device__ __nv_bfloat16 g_Eh[RR*DD];
__device__ __nv_bfloat16 g_Eth[DD*RR];
__device__ __nv_bfloat16 g_Hbh[(long)NC*RR*RR];

// ---------------- helpers ----------------
__device__ __forceinline__ float tf32r(float x) {
    unsigned u;
    asm("cvt.rna.tf32.f32 %0, %1;" : "=r"(u) : "f"(x));
    return __uint_as_float(u);
}
__device__ __forceinline__ void mma_tf32(float* c, const unsigned* a, const unsigned* b) {
    asm volatile(
        "mma.sync.aligned.m16n8k8.row.col.f32.tf32.tf32.f32 "
        "{%0,%1,%2,%3}, {%4,%5,%6,%7}, {%8,%9}, {%0,%1,%2,%3};\n"
        : "+f"(c[0]), "+f"(c[1]), "+f"(c[2]), "+f"(c[3])
        : "r"(a[0]), "r"(a[1]), "r"(a[2]), "r"(a[3]), "r"(b[0]), "r"(b[1]));
}
__device__ __forceinline__ void mma_bf16(float* c, const unsigned* a, const unsigned* b) {
    asm volatile(
        "mma.sync.aligned.m16n8k16.row.col.f32.bf16.bf16.f32 "
        "{%0,%1,%2,%3}, {%4,%5,%6,%7}, {%8,%9}, {%0,%1,%2,%3};\n"
        : "+f"(c[0]), "+f"(c[1]), "+f"(c[2]), "+f"(c[3])
        : "r"(a[0]), "r"(a[1]), "r"(a[2]), "r"(a[3]), "r"(b[0]), "r"(b[1]));
}
__device__ __forceinline__ void ldsm4(unsigned& r0, unsigned& r1, unsigned& r2,
                                      unsigned& r3, unsigned addr) {
    asm volatile("ldmatrix.sync.aligned.m8n8.x4.shared.b16 {%0,%1,%2,%3},[%4];"
                 : "=r"(r0), "=r"(r1), "=r"(r2), "=r"(r3) : "r"(addr));
}
__device__ __forceinline__ void ldsm4t(unsigned& r0, unsigned& r1, unsigned& r2,
                                       unsigned& r3, unsigned addr) {
    asm volatile("ldmatrix.sync.aligned.m8n8.x4.trans.shared.b16 {%0,%1,%2,%3},[%4];"
                 : "=r"(r0), "=r"(r1), "=r"(r2), "=r"(r3) : "r"(addr));
}

// ---------------- elementwise kernels ----------------
__global__ void k_prep(const float* __restrict__ x, const float* __restrict__ a1,
                       float* __restrict__ HT) {
    long i4 = (long)blockIdx.x * blockDim.x + threadIdx.x;
    long flat = i4 * 4;
    int b = (int)(flat / ((long)SS*DD));
    int t = (int)((flat / DD) % SS);
    int d = (int)(flat % DD);
    float4 xv = *(const float4*)(x + flat);
    float4 av = *(const float4*)(a1 + d);
    float4 o;
    o.x = tanhf(av.x * xv.x); o.y = tanhf(av.y * xv.y);
    o.z = tanhf(av.z * xv.z); o.w = tanhf(av.w * xv.w);
    *(float4*)(HT + ((long)(t*BB + b) * DD + d)) = o;
}

__global__ void k_tv(const float* __restrict__ ST, const float* __restrict__ noise,
                     float* __restrict__ TV, __nv_bfloat16* __restrict__ TVh) {
    long i4 = (long)blockIdx.x * blockDim.x + threadIdx.x;
    long flat = i4 * 4;
    int t = (int)(flat / ((long)BB*DD));
    int b = (int)((flat / DD) % BB);
    int d = (int)(flat % DD);
    float4 s = *(const float4*)(ST + flat);
    float4 n = *(const float4*)(noise + ((long)b*SS + t) * DD + d);
    float4 o; o.x = s.x+n.x; o.y = s.y+n.y; o.z = s.z+n.z; o.w = s.w+n.w;
    *(float4*)(TV + flat) = o;
    *(__nv_bfloat162*)(TVh + flat)     = __floats2bfloat162_rn(o.x, o.y);
    *(__nv_bfloat162*)(TVh + flat + 2) = __floats2bfloat162_rn(o.z, o.w);
}

__global__ void k_copyW(const float* __restrict__ src, float* __restrict__ dst) {
    long i4 = (long)blockIdx.x * blockDim.x + threadIdx.x;
    *(float4*)(dst + i4*4) = *(const float4*)(src + i4*4);
}

__global__ void k_x1h2(const float* __restrict__ OT, const float* __restrict__ x,
                       const float* __restrict__ a2,
                       float* __restrict__ X1, float* __restrict__ H2) {
    long i4 = (long)blockIdx.x * blockDim.x + threadIdx.x;
    long flat = i4 * 4;
    int b = (int)(flat / ((long)SS*DD));
    int t = (int)((flat / DD) % SS);
    int d = (int)(flat % DD);
    float4 ro = *(const float4*)(OT + ((long)(t*BB + b) * DD + d));
    float4 xv = *(const float4*)(x + flat);
    float4 av = *(const float4*)(a2 + d);
    float4 x1; x1.x = ro.x+xv.x; x1.y = ro.y+xv.y; x1.z = ro.z+xv.z; x1.w = ro.w+xv.w;
    *(float4*)(X1 + flat) = x1;
    float4 h; h.x = tanhf(av.x*x1.x); h.y = tanhf(av.y*x1.y);
    h.z = tanhf(av.z*x1.z); h.w = tanhf(av.w*x1.w);
    *(float4*)(H2 + flat) = h;
}

// ---------------- forward substitution (RR=512, 32 steps) ----------------
__global__ void __launch_bounds__(256) solve_k(const float* __restrict__ A,
                                               const float* __restrict__ G,
                                               __nv_bfloat16* __restrict__ Eh,
                                               __nv_bfloat16* __restrict__ Eth) {
    __shared__ __align__(16) float Es[16][RR + 4];
    const int j0 = blockIdx.x * 16;
    const int tid = threadIdx.x;
    const int r = tid >> 4, j = tid & 15;
    #pragma unroll
    for (int i = 0; i < CSTEPS; ++i) {
        int row = i*16 + r;
        Es[j][row] = A[(long)row * DD + j0 + j];
    }
    __syncthreads();
    for (int t = 1; t < CSTEPS; ++t) {
        const int row = t*16 + r;
        const float* Gr = G + (long)row * RR;
        const int kmax = t * 16;
        float sx=0.f, sy=0.f, sz=0.f, sw=0.f;
        for (int k = 0; k < kmax; k += 4) {
            float4 g = *(const float4*)(Gr + k);
            float4 e = *(const float4*)&Es[j][k];
            sx = fmaf(g.x, e.x, sx); sy = fmaf(g.y, e.y, sy);
            sz = fmaf(g.z, e.z, sz); sw = fmaf(g.w, e.w, sw);
        }
        float v = Es[j][row] - ETA_F * ((sx+sy)+(sz+sw));
        Es[j][row] = v;
        __syncthreads();
    }
    #pragma unroll
    for (int i = 0; i < CSTEPS; ++i) {
        int row = i*16 + r;
        __nv_bfloat16 hv = __float2bfloat16(Es[j][row]);
        Eh[(long)row * DD + j0 + j] = hv;
        Eth[(long)(j0 + j) * RR + row] = hv;
    }
}

// ---------------- tf32 tensor-core GEMM (R3, proven) ----------
// OPA: 0 = A[M,K] row-major; 1 = A stored [K,M]; 2 = dual-source rows
// OPB: 0 = C = A*B^T, B[N,K]; 1 = C = A*B, B[K,N]
// MODE: 0 plain  1 sub P1 on rows<RR  5 gelu  6 C=P1*acc+P2  7 plain + bf16 copy->P2
template<int BM,int BN,int MW,int NW,int OPA,int OPB,int MODE>
__global__ void __launch_bounds__(MW*NW*32, (MW*NW*32==256) ? 2 : 3)
gemm_t(const float* __restrict__ A, const float* __restrict__ A2, int lda,
       const float* __restrict__ B, int ldb,
       float* __restrict__ C, int ldc,
       int M, int N, int K,
       const float* __restrict__ P1, const float* __restrict__ P2,
       long saz, long sbz, long scz)
{
    constexpr int BK  = 16;
    constexpr int BKp = 20;
    constexpr int T   = MW*NW*32;
    constexpr int WM  = BM/MW, WN = BN/NW;
    constexpr int MT  = WM/16, NT = WN/8;
    constexpr int LPA = BM*BK/(4*T);
    constexpr int LPB = BN*BK/(4*T);

    const int m0 = blockIdx.y * BM, n0 = blockIdx.x * BN;
    const int bz = blockIdx.z;
    A += (long)bz * saz;
    B += (long)bz * sbz;
    C += (long)bz * scz;

    __shared__ __align__(16) float As[2][BM][BKp];
    __shared__ __align__(16) float Bs[2][BN][BKp];

    const int tid  = threadIdx.x;
    const int lane = tid & 31;
    const int wid  = tid >> 5;
    const int wm   = wid / NW, wn = wid % NW;
    const int mw0  = wm * WM, nw0 = wn * WN;
    const int qr   = lane >> 2;
    const int qc   = lane & 3;
    const int lr   = lane & 7;
    const int aBase = (mw0 + lr + ((lane>>3)&1)*8) * BKp + ((lane>>4)&1)*4;
    const int bBase = (nw0 + lr + ((lane>>4)&1)*8) * BKp + ((lane>>3)&1)*4;

    float acc[MT][NT][4];
    #pragma unroll
    for (int i = 0; i < MT; ++i)
        #pragma unroll
        for (int j = 0; j < NT; ++j)
            #pragma unroll
            for (int q = 0; q < 4; ++q) acc[i][j][q] = 0.f;

    const int ktiles = K / BK;
    float4 pa[LPA], pb[LPB];

    auto gload = [&](int k0) {
        #pragma unroll
        for (int p = 0; p < LPA; ++p) {
            const int idx = tid + p*T;
            if (OPA == 1) {
                const int ak = idx / (BM/4), amq = idx % (BM/4);
                pa[p] = *(const float4*)(A + (long)(k0 + ak) * lda + m0 + 4*amq);
            } else {
                const int am = idx / (BK/4), akq = idx % (BK/4);
                const int mg = m0 + am;
                const float* Ar;
                if (OPA == 2) Ar = (mg < RR) ? (A + (long)mg * lda)
                                             : (A2 + (long)(mg - RR) * lda);
                else          Ar = A + (long)mg * lda;
                pa[p] = *(const float4*)(Ar + k0 + 4*akq);
            }
        }
        #pragma unroll
        for (int p = 0; p < LPB; ++p) {
            const int idx = tid + p*T;
            if (OPB == 1) {
                const int bk = idx / (BN/4), bnq = idx % (BN/4);
                pb[p] = *(const float4*)(B + (long)(k0 + bk) * ldb + n0 + 4*bnq);
            } else {
                const int bn = idx / (BK/4), bkq = idx % (BK/4);
                pb[p] = *(const float4*)(B + (long)(n0 + bn) * ldb + k0 + 4*bkq);
            }
        }
    };
    auto sstore = [&](int s) {
        #pragma unroll
        for (int p = 0; p < LPA; ++p) {
            const int idx = tid + p*T;
            if (OPA == 1) {
                const int ak = idx / (BM/4), amq = idx % (BM/4);
                As[s][4*amq+0][ak] = tf32r(pa[p].x);
                As[s][4*amq+1][ak] = tf32r(pa[p].y);
                As[s][4*amq+2][ak] = tf32r(pa[p].z);
                As[s][4*amq+3][ak] = tf32r(pa[p].w);
            } else {
                const int am = idx / (BK/4), akq = idx % (BK/4);
                float4 w = make_float4(tf32r(pa[p].x), tf32r(pa[p].y),
                                       tf32r(pa[p].z), tf32r(pa[p].w));
                *(float4*)&As[s][am][4*akq] = w;
            }
        }
        #pragma unroll
        for (int p = 0; p < LPB; ++p) {
            const int idx = tid + p*T;
            if (OPB == 1) {
                const int bk = idx / (BN/4), bnq = idx % (BN/4);
                Bs[s][4*bnq+0][bk] = tf32r(pb[p].x);
                Bs[s][4*bnq+1][bk] = tf32r(pb[p].y);
                Bs[s][4*bnq+2][bk] = tf32r(pb[p].z);
                Bs[s][4*bnq+3][bk] = tf32r(pb[p].w);
            } else {
                const int bn = idx / (BK/4), bkq = idx % (BK/4);
                float4 w = make_float4(tf32r(pb[p].x), tf32r(pb[p].y),
                                       tf32r(pb[p].z), tf32r(pb[p].w));
                *(float4*)&Bs[s][bn][4*bkq] = w;
            }
        }
    };
    auto compute = [&](int s) {
        const unsigned sA = (unsigned)__cvta_generic_to_shared(&As[s][0][0]);
        const unsigned sB = (unsigned)__cvta_generic_to_shared(&Bs[s][0][0]);
        #pragma unroll
        for (int ks = 0; ks < BK; ks += 8) {
            unsigned af[MT][4];
            #pragma unroll
            for (int im = 0; im < MT; ++im)
                ldsm4(af[im][0], af[im][1], af[im][2], af[im][3],
                      sA + 4u*(aBase + im*16*BKp + ks));
            unsigned bf[NT][2];
            #pragma unroll
            for (int jp = 0; jp < NT/2; ++jp) {
                unsigned r0, r1, r2, r3;
                ldsm4(r0, r1, r2, r3, sB + 4u*(bBase + jp*16*BKp + ks));
                bf[2*jp][0] = r0; bf[2*jp][1] = r1;
                bf[2*jp+1][0] = r2; bf[2*jp+1][1] = r3;
            }
            #pragma unroll
            for (int im = 0; im < MT; ++im)
                #pragma unroll
                for (int jn = 0; jn < NT; ++jn)
                    mma_tf32(acc[im][jn], af[im], bf[jn]);
        }
    };

    gload(0);
    sstore(0);
    __syncthreads();

    for (int kt = 0; kt < ktiles; ++kt) {
        const bool more = (kt + 1 < ktiles);
        if (more) gload((kt+1)*BK);
        compute(kt & 1);
        if (more) sstore((kt+1) & 1);
        __syncthreads();
    }

    #pragma unroll
    for (int im = 0; im < MT; ++im) {
        #pragma unroll
        for (int jn = 0; jn < NT; ++jn) {
            #pragma unroll
            for (int h = 0; h < 2; ++h) {
                const int m = m0 + mw0 + im*16 + qr + h*8;
                const int n = n0 + nw0 + jn*8 + qc*2;
                const long ci = (long)m * ldc + n;
                float v0 = acc[im][jn][h*2 + 0];
                float v1 = acc[im][jn][h*2 + 1];
                if (MODE == 0) {
                    C[ci] = v0; C[ci+1] = v1;
                } else if (MODE == 1) {
                    if (m < RR) {
                        v0 -= P1[(long)m * ldc + n];
                        v1 -= P1[(long)m * ldc + n + 1];
                    }
                    C[ci] = v0; C[ci+1] = v1;
                } else if (MODE == 5) {
                    C[ci]   = 0.5f * v0 * (1.f + erff(v0 * 0.70710678118654752f));
                    C[ci+1] = 0.5f * v1 * (1.f + erff(v1 * 0.70710678118654752f));
                } else if (MODE == 6) {
                    C[ci]   = P1[ci]   * v0 + P2[ci];
                    C[ci+1] = P1[ci+1] * v1 + P2[ci+1];
                } else if (MODE == 7) {
                    C[ci] = v0; C[ci+1] = v1;
                    __nv_bfloat16* Cb = (__nv_bfloat16*)P2;
                    *(__nv_bfloat162*)(Cb + ci) = __floats2bfloat162_rn(v0, v1);
                }
            }
        }
    }
}

// ---------------- bf16 tensor-core GEMM (eta-suppressed paths) ----------
// A row-major [M,K] bf16. OPB: 0 = B[N,K] (NT); 1 = B[K,N] (NN).
// MODE: 2 block-tril mask (+skip upper tiles)  3 C=P1-ETA*acc (tril-K)  4 C-=ETA*acc
// OUTT: 0 fp32 out (C), 1 bf16 out (Ch)
template<int OPB,int MODE,int OUTT>
__global__ void __launch_bounds__(256, 3)
gemm_h(const __nv_bfloat16* __restrict__ A, long lda,
       const __nv_bfloat16* __restrict__ B, long ldb,
       float* __restrict__ C, __nv_bfloat16* __restrict__ Ch, long ldc,
       int K, const float* __restrict__ P1,
       long saz, long sbz, long scz)
{
    constexpr int BM = 128, BN = 64, BK = 16;
    constexpr int MT = 2, NT = 4;     // warp tile 32x32, warps 4(m) x 2(n)
    const int m0 = blockIdx.y * BM, n0 = blockIdx.x * BN;
    if (MODE == 2 && n0 >= m0 + BM) return;

    A += (long)blockIdx.z * saz;
    B += (long)blockIdx.z * sbz;
    if (OUTT == 0) C  += (long)blockIdx.z * scz;
    else           Ch += (long)blockIdx.z * scz;

    __shared__ __align__(16) __nv_bfloat16 AsS[2][BM*24];     // stride 24
    __shared__ __align__(16) __nv_bfloat16 BsS[2][1536];      // OPB0: [BN][24]; OPB1: [BK][72]

    const int tid = threadIdx.x;
    const int lane = tid & 31;
    const int wid = tid >> 5;
    const int wm = wid >> 1, wn = wid & 1;
    const int mw0 = wm * 32, nw0 = wn * 32;
    const int qr = lane >> 2, qc = lane & 3;

    float acc[MT][NT][4];
    #pragma unroll
    for (int i = 0; i < MT; ++i)
        #pragma unroll
        for (int j = 0; j < NT; ++j)
            #pragma unroll
            for (int q = 0; q < 4; ++q) acc[i][j][q] = 0.f;

    int Kl = K;
    if (MODE == 3) { int t = m0 + BM; Kl = t < K ? t : K; }
    const int ktiles = Kl / BK;

    uint4 pa, pb;
    auto gload = [&](int kt) {
        const long k0 = (long)kt * BK;
        const int row = tid >> 1, half = tid & 1;
        pa = *(const uint4*)(A + (long)(m0 + row) * lda + k0 + half*8);
        if (tid < 128) {
            if (OPB == 0) {
                const int r = tid >> 1, h = tid & 1;
                pb = *(const uint4*)(B + (long)(n0 + r) * ldb + k0 + h*8);
            } else {
                const int kk = tid >> 3, nc = tid & 7;
                pb = *(const uint4*)(B + (k0 + kk) * ldb + n0 + nc*8);
            }
        }
    };
    auto sstore = [&](int s) {
        const int row = tid >> 1, half = tid & 1;
        *(uint4*)(&AsS[s][row*24 + half*8]) = pa;
        if (tid < 128) {
            if (OPB == 0) {
                const int r = tid >> 1, h = tid & 1;
                *(uint4*)(&BsS[s][r*24 + h*8]) = pb;
            } else {
                const int kk = tid >> 3, nc = tid & 7;
                *(uint4*)(&BsS[s][kk*72 + nc*8]) = pb;
            }
        }
    };
    auto compute = [&](int s) {
        const unsigned sA = (unsigned)__cvta_generic_to_shared(&AsS[s][0]);
        const unsigned sB = (unsigned)__cvta_generic_to_shared(&BsS[s][0]);
        const int g = lane >> 3;
        unsigned af[MT][4];
        #pragma unroll
        for (int im = 0; im < MT; ++im) {
            const int row = mw0 + im*16 + (g & 1)*8 + (lane & 7);
            const int kb = (g >> 1)*8;
            ldsm4(af[im][0], af[im][1], af[im][2], af[im][3],
                  sA + 2u*(row*24 + kb));
        }
        unsigned bf[NT][2];
        #pragma unroll
        for (int jp = 0; jp < 2; ++jp) {
            unsigned r0, r1, r2, r3;
            if (OPB == 0) {
                const int row = nw0 + jp*16 + (g >> 1)*8 + (lane & 7);
                const int kb = (g & 1)*8;
                ldsm4(r0, r1, r2, r3, sB + 2u*(row*24 + kb));
            } else {
                const int krow = (g & 1)*8 + (lane & 7);
                const int col = nw0 + jp*16 + (g >> 1)*8;
                ldsm4t(r0, r1, r2, r3, sB + 2u*(krow*72 + col));
            }
            bf[2*jp][0] = r0; bf[2*jp][1] = r1;
            bf[2*jp+1][0] = r2; bf[2*jp+1][1] = r3;
        }
        #pragma unroll
        for (int im = 0; im < MT; ++im)
            #pragma unroll
            for (int jn = 0; jn < NT; ++jn)
                mma_bf16(acc[im][jn], af[im], bf[jn]);
    };

    gload(0);
    sstore(0);
    __syncthreads();
    for (int kt = 0; kt < ktiles; ++kt) {
        const bool more = (kt + 1 < ktiles);
        if (more) gload(kt + 1);
        compute(kt & 1);
        if (more) sstore((kt + 1) & 1);
        __syncthreads();
    }

    #pragma unroll
    for (int im = 0; im < MT; ++im) {
        #pragma unroll
        for (int jn = 0; jn < NT; ++jn) {
            #pragma unroll
            for (int h = 0; h < 2; ++h) {
                const int m = m0 + mw0 + im*16 + qr + h*8;
                const int n = n0 + nw0 + jn*8 + qc*2;
                const long ci = (long)m * ldc + n;
                float v0 = acc[im][jn][h*2 + 0];
                float v1 = acc[im][jn][h*2 + 1];
                if (MODE == 2) {
                    const bool z = ((n >> 4) > (m >> 4));
                    if (z) { v0 = 0.f; v1 = 0.f; }
                    if (OUTT == 1)
                        *(__nv_bfloat162*)(Ch + ci) = __floats2bfloat162_rn(v0, v1);
                    else { C[ci] = v0; C[ci+1] = v1; }
                } else if (MODE == 3) {
                    float2 p = *(const float2*)(P1 + (long)m * ldc + n);
                    C[ci]   = p.x - ETA_F * v0;
                    C[ci+1] = p.y - ETA_F * v1;
                } else if (MODE == 4) {
                    float2 c = *(const float2*)(C + ci);
                    C[ci]   = c.x - ETA_F * v0;
                    C[ci+1] = c.y - ETA_F * v1;
                }
            }
        }
    }
}

// ---------------- host side ----------------
extern "C" void kernel_launch(void* const* d_in, const int* in_sizes, int n_in,
                              void* d_out, int out_size) {
    const float* x      = (const float*)d_in[0];
    const float* noise  = (const float*)d_in[1];
    const float* alpha1 = (const float*)d_in[2];
    const float* alpha2 = (const float*)d_in[3];
    const float* W_map  = (const float*)d_in[4];
    const float* W_st   = (const float*)d_in[5];
    const float* W_pr   = (const float*)d_in[6];
    const float* W_p1   = (const float*)d_in[7];
    const float* W_p2   = (const float*)d_in[8];
    float* out = (float*)d_out;

    float *HT, *ST, *TV, *PR, *OT, *X1, *H2, *U, *W, *AP, *Gb;
    __nv_bfloat16 *TVh, *PRh, *Eh, *Eth, *Hbh;
    cudaGetSymbolAddress((void**)&HT, g_HT);
    cudaGetSymbolAddress((void**)&ST, g_STATE);
    cudaGetSymbolAddress((void**)&TV, g_TV);
    cudaGetSymbolAddress((void**)&PR, g_PROBE);
    cudaGetSymbolAddress((void**)&OT, g_OT);
    cudaGetSymbolAddress((void**)&X1, g_X1);
    cudaGetSymbolAddress((void**)&H2, g_H2);
    cudaGetSymbolAddress((void**)&U,  g_U);
    cudaGetSymbolAddress((void**)&W,  g_W);
    cudaGetSymbolAddress((void**)&AP, g_AP);
    cudaGetSymbolAddress((void**)&Gb, g_Gb);
    cudaGetSymbolAddress((void**)&TVh, g_TVh);
    cudaGetSymbolAddress((void**)&PRh, g_PRh);
    cudaGetSymbolAddress((void**)&Eh,  g_Eh);
    cudaGetSymbolAddress((void**)&Eth, g_Eth);
    cudaGetSymbolAddress((void**)&Hbh, g_Hbh);

    const int EW_BLKS = (SB*DD/4) / 256;

    // 0: h = tanh(alpha1*x), time-major
    k_prep<<<EW_BLKS, 256>>>(x, alpha1, HT);
    // 1: W = W_map
    k_copyW<<<(DD*DD/4)/256, 256>>>(W_map, W);
    // 2: STATE (tf32)
    gemm_t<128,128,2,4,0,0,0><<<dim3(DD/128, SB/128, 1), 256>>>(
        HT, nullptr, DD, W_st, DD, ST, DD, SB, DD, DD, nullptr, nullptr, 0,0,0);
    // 3: PROBE (tf32, + bf16 copy -> PRh)     [profiled launch]
    gemm_t<128,128,2,4,0,0,7><<<dim3(DD/128, SB/128, 1), 256>>>(
        HT, nullptr, DD, W_pr, DD, PR, DD, SB, DD, DD, nullptr, (const float*)PRh, 0,0,0);
    // 4: TV = STATE + noise (fp32 + bf16)
    k_tv<<<EW_BLKS, 256>>>(ST, noise, TV, TVh);
    // 5/6: batched block-tril Gram (fp32 out) + cross-Gram (bf16 out)
    gemm_h<0,2,0><<<dim3(RR/64, RR/128, NC), 256>>>(
        TVh, DD, TVh, DD, Gb, nullptr, RR, DD, nullptr,
        (long)RR*DD, (long)RR*DD, (long)RR*RR);
    gemm_h<0,2,1><<<dim3(RR/64, RR/128, NC), 256>>>(
        PRh, DD, TVh, DD, nullptr, Hbh, RR, DD, nullptr,
        (long)RR*DD, (long)RR*DD, (long)RR*RR);

    // chunk loop (32 chunks)
    for (int c = 0; c < NC; ++c) {
        const float* TVc = TV + (long)c*RR*DD;
        const float* PRc = PR + (long)c*RR*DD;
        const float* STc = ST + (long)c*RR*DD;
        // A = TVc@W^T - STATEc (rows<RR) ; P0 = PRc@W^T (rows>=RR)   [tf32]
        gemm_t<64,64,2,2,2,0,1><<<dim3(DD/64, (2*RR)/64, 1), 128>>>(
            TVc, PRc, DD, W, DD, AP, DD, 2*RR, DD, DD, STc, nullptr, 0,0,0);
        // forward substitution -> Eh, Eth (bf16)
        solve_k<<<DD/16, 256>>>(AP, Gb + (long)c*RR*RR, Eh, Eth);
        // readout = P0 - ETA * trilHb @ E    [bf16: A=Hbh, B=Eh (K,N)]
        gemm_h<1,3,0><<<dim3(DD/64, RR/128, 1), 256>>>(
            Hbh + (long)c*RR*RR, RR, Eh, DD,
            OT + (long)c*RR*DD, nullptr, DD, RR,
            AP + (long)RR*DD, 0,0,0);
        // W -= ETA * E^T @ TVc               [bf16: A=Eth, B=TVh chunk (K,N)]
        gemm_h<1,4,0><<<dim3(DD/64, DD/128, 1), 256>>>(
            Eth, RR, TVh + (long)c*RR*DD, DD,
            W, nullptr, DD, RR, nullptr, 0,0,0);
    }

    // x1 / h2
    k_x1h2<<<EW_BLKS, 256>>>(OT, x, alpha2, X1, H2);
    // U = gelu(h2 @ Wp1^T)   [tf32]
    gemm_t<128,128,2,4,0,0,5><<<dim3(DD/128, SB/128, 1), 256>>>(
        H2, nullptr, DD, W_p1, DD, U, DD, SB, DD, DD, nullptr, nullptr, 0,0,0);
    // out = U * (h2 @ Wp2^T) + X1   [tf32]
    gemm_t<128,128,2,4,0,0,6><<<dim3(DD/128, SB/128, 1), 256>>>(
        H2, nullptr, DD, W_p2, DD, out, DD, SB, DD, DD, U, X1, 0,0,0);
}